// round 10
// baseline (speedup 1.0000x reference)
#include <cuda_runtime.h>
#include <cstdint>

#define NQ   12
#define DIM  4096
#define NT   256

typedef unsigned long long ull;

// Packed broadcast gate constants (written by prep kernel each launch).
// d_g1[l][w][0..17]: 1q gate coeff packs; d_gc[l][w][0..5]: CRX coeff packs.
__device__ ull d_g1[2][NQ][18];
__device__ ull d_gc[2][NQ][6];

__device__ __forceinline__ float2 cmulf(float2 a, float2 b) {
    return make_float2(a.x * b.x - a.y * b.y, a.x * b.y + a.y * b.x);
}
__device__ __forceinline__ ull pk2(float lo, float hi) {
    return (ull)__float_as_uint(lo) | ((ull)__float_as_uint(hi) << 32);
}

// ---- packed f32x2 ops (Blackwell FFMA2 path, PTX-only) ----
__device__ __forceinline__ ull f2fma(ull a, ull b, ull c) {
    ull d; asm("fma.rn.f32x2 %0, %1, %2, %3;" : "=l"(d) : "l"(a), "l"(b), "l"(c));
    return d;
}
__device__ __forceinline__ ull f2mul(ull a, ull b) {
    ull d; asm("mul.rn.f32x2 %0, %1, %2;" : "=l"(d) : "l"(a), "l"(b));
    return d;
}
__device__ __forceinline__ ull pkr(float lo, float hi) {
    ull r; asm("mov.b64 %0, {%1, %2};" : "=l"(r) : "f"(lo), "f"(hi));
    return r;
}
__device__ __forceinline__ void upk(ull v, float& lo, float& hi) {
    asm("mov.b64 {%0, %1}, %2;" : "=f"(lo), "=f"(hi) : "l"(v));
}

// ---------------------------------------------------------------------------
__global__ void prep_gates(const float* __restrict__ angles) {
    int t = threadIdx.x;
    if (t >= 24) return;
    int l = t / NQ;
    int i = t % NQ;
    int base = l * 48;
    float ax = angles[base + i];
    float ay = angles[base + NQ + i];
    float az = angles[base + 2 * NQ + i];

    float cx = cosf(0.5f * ax), sx = sinf(0.5f * ax);
    float cy = cosf(0.5f * ay), sy = sinf(0.5f * ay);
    float cz = cosf(0.5f * az), sz = sinf(0.5f * az);

    float2 m00 = make_float2(cy * cx,  sy * sx);
    float2 m01 = make_float2(-sy * cx, -cy * sx);
    float2 m10 = make_float2(sy * cx,  -cy * sx);
    float2 m11 = make_float2(cy * cx,  -sy * sx);
    float2 em = make_float2(cz, -sz);
    float2 ep = make_float2(cz,  sz);
    float2 u00 = cmulf(em, m00);
    float2 u01 = cmulf(em, m01);
    float2 u10 = cmulf(ep, m10);
    float2 u11 = cmulf(ep, m11);

    ull* g1 = d_g1[l][i];
    // broadcast packs for slot-bit 1q gates
    g1[0]  = pk2(u00.x, u00.x);  g1[1]  = pk2(u00.y, u00.y);  g1[2]  = pk2(-u00.y, -u00.y);
    g1[3]  = pk2(u01.x, u01.x);  g1[4]  = pk2(u01.y, u01.y);  g1[5]  = pk2(-u01.y, -u01.y);
    g1[6]  = pk2(u10.x, u10.x);  g1[7]  = pk2(u10.y, u10.y);  g1[8]  = pk2(-u10.y, -u10.y);
    g1[9]  = pk2(u11.x, u11.x);  g1[10] = pk2(u11.y, u11.y);  g1[11] = pk2(-u11.y, -u11.y);
    // row packs for pack-bit (k3) 1q gates
    g1[12] = pk2(u00.x, u10.x);  g1[13] = pk2(u00.y, u10.y);  g1[14] = pk2(-u00.y, -u10.y);
    g1[15] = pk2(u01.x, u11.x);  g1[16] = pk2(u01.y, u11.y);  g1[17] = pk2(-u01.y, -u11.y);

    int g = (l == 0) ? (36 + i) : (84 + (NQ - 1 - i));
    float th = angles[g];
    float cc = cosf(0.5f * th), ss = sinf(0.5f * th);
    ull* gc = d_gc[l][i];
    gc[0] = pk2(cc, cc);   gc[1] = pk2(ss, ss);   gc[2] = pk2(-ss, -ss);
    gc[3] = pk2(1.f, cc);  gc[4] = pk2(0.f, ss);  gc[5] = pk2(0.f, -ss);
}

// ---------------------------------------------------------------------------
// Layout configs (identical to verified R3 kernel). Address bit b <-> wire (11-b).
//  cfg 0 (A): local bits {8,9,10,11}   cfg 1 (B): {5,6,7,8}   cfg 2 (C): {2,3,4,5}
//  cfg 3 (D): {0,1,2,11}               cfg 4 (E): {4,5,6,7}   cfg 5 (F): {0,1,2,3}
// p = a + (a>>4) padding keeps every config's pattern bank-conflict-free.
__device__ __forceinline__ int padidx(int a) { return a + (a >> 4); }

template<int CFG>
__device__ __forceinline__ int baseof(int lane, int warp) {
    if (CFG == 0) return lane | (warp << 5);
    if (CFG == 1) return lane | (warp << 9);
    if (CFG == 2) return (lane & 3) | ((lane >> 2) << 6) | (warp << 9);
    if (CFG == 3) return (lane << 3) | (warp << 8);
    if (CFG == 4) return (lane & 15) | ((lane >> 4) << 8) | (warp << 9);
    return (lane << 4) | (warp << 9);
}
template<int CFG>
__device__ __forceinline__ int placeof(int j) {
    if (CFG == 0) return j << 8;
    if (CFG == 1) return j << 5;
    if (CFG == 2) return j << 2;
    if (CFG == 3) return (j & 7) | ((j >> 3) << 11);
    if (CFG == 4) return j << 4;
    return j;
}

// State: vre[m], vim[m], m = local bits k2k1k0; each u64 = (k3=0, k3=1) halves.
template<int CX, int CY>
__device__ __forceinline__ void remap(ull* vre, ull* vim, float2* s, int lane, int warp) {
    const int bx = baseof<CX>(lane, warp);
    #pragma unroll
    for (int m = 0; m < 8; m++) {
        float rl, rh, il, ih;
        upk(vre[m], rl, rh);
        upk(vim[m], il, ih);
        s[padidx(bx | placeof<CX>(m))]     = make_float2(rl, il);
        s[padidx(bx | placeof<CX>(m | 8))] = make_float2(rh, ih);
    }
    __syncthreads();
    const int by = baseof<CY>(lane, warp);
    #pragma unroll
    for (int m = 0; m < 8; m++) {
        float2 lo = s[padidx(by | placeof<CY>(m))];
        float2 hi = s[padidx(by | placeof<CY>(m | 8))];
        vre[m] = pkr(lo.x, hi.x);
        vim[m] = pkr(lo.y, hi.y);
    }
    __syncthreads();
}

// fused 1q gate on slot bit K in {0,1,2} — fully packed
template<int K>
__device__ __forceinline__ void pgate1q(ull* vre, ull* vim, const ull* c) {
    const ull c0 = c[0], c1 = c[1], c2 = c[2], c3 = c[3], c4 = c[4], c5 = c[5];
    const ull c6 = c[6], c7 = c[7], c8 = c[8], c9 = c[9], c10 = c[10], c11 = c[11];
    #pragma unroll
    for (int m = 0; m < 8; m++) {
        if (((m >> K) & 1) == 0) {
            int m1 = m | (1 << K);
            ull r0 = vre[m], i0 = vim[m], r1 = vre[m1], i1 = vim[m1];
            vre[m]  = f2fma(c0, r0, f2fma(c2, i0, f2fma(c3, r1, f2mul(c5, i1))));
            vim[m]  = f2fma(c0, i0, f2fma(c1, r0, f2fma(c3, i1, f2mul(c4, r1))));
            vre[m1] = f2fma(c6, r0, f2fma(c8, i0, f2fma(c9, r1, f2mul(c11, i1))));
            vim[m1] = f2fma(c6, i0, f2fma(c7, r0, f2fma(c9, i1, f2mul(c10, r1))));
        }
    }
}

// fused 1q gate on pack bit k3 — row-packed coefficients
__device__ __forceinline__ void pgate1q_k3(ull* vre, ull* vim, const ull* c) {
    const ull P1 = c[12], P2 = c[13], nP2 = c[14], P3 = c[15], P4 = c[16], nP4 = c[17];
    #pragma unroll
    for (int m = 0; m < 8; m++) {
        float rl, rh, il, ih;
        upk(vre[m], rl, rh);
        upk(vim[m], il, ih);
        ull RL = pkr(rl, rl), RH = pkr(rh, rh), IL = pkr(il, il), IH = pkr(ih, ih);
        vre[m] = f2fma(P1, RL, f2fma(nP2, IL, f2fma(P3, RH, f2mul(nP4, IH))));
        vim[m] = f2fma(P1, IL, f2fma(P2, RL, f2fma(P3, IH, f2mul(P4, RH))));
    }
}

// CRX, control bit CK and target bit TK both slot bits — fully packed
template<int CK, int TK>
__device__ __forceinline__ void pcrx(ull* vre, ull* vim, const ull* gc) {
    const ull ccb = gc[0], ssb = gc[1], nssb = gc[2];
    #pragma unroll
    for (int m = 0; m < 8; m++) {
        if (((m >> CK) & 1) == 1 && ((m >> TK) & 1) == 0) {
            int m1 = m | (1 << TK);
            ull r0 = vre[m], i0 = vim[m], r1 = vre[m1], i1 = vim[m1];
            vre[m]  = f2fma(ccb, r0, f2mul(ssb, i1));
            vim[m]  = f2fma(ccb, i0, f2mul(nssb, r1));
            vre[m1] = f2fma(ccb, r1, f2mul(ssb, i0));
            vim[m1] = f2fma(ccb, i1, f2mul(nssb, r0));
        }
    }
}

// CRX with control = pack bit k3: lane coefficients (1,cc)/(0,ss) -> lo lane identity
template<int TK>
__device__ __forceinline__ void pcrx_c3(ull* vre, ull* vim, const ull* gc) {
    const ull C3 = gc[3], S3 = gc[4], nS3 = gc[5];
    #pragma unroll
    for (int m = 0; m < 8; m++) {
        if (((m >> TK) & 1) == 0) {
            int m1 = m | (1 << TK);
            ull r0 = vre[m], i0 = vim[m], r1 = vre[m1], i1 = vim[m1];
            vre[m]  = f2fma(C3, r0, f2mul(S3, i1));
            vim[m]  = f2fma(C3, i0, f2mul(nS3, r1));
            vre[m1] = f2fma(C3, r1, f2mul(S3, i0));
            vim[m1] = f2fma(C3, i1, f2mul(nS3, r0));
        }
    }
}

// CRX with target = pack bit k3: half-swap trick on slots with control bit CK=1
template<int CK>
__device__ __forceinline__ void pcrx_t3(ull* vre, ull* vim, const ull* gc) {
    const ull ccb = gc[0], ssb = gc[1], nssb = gc[2];
    #pragma unroll
    for (int m = 0; m < 8; m++) {
        if (((m >> CK) & 1) == 1) {
            float rl, rh, il, ih;
            upk(vre[m], rl, rh);
            upk(vim[m], il, ih);
            ull resw = pkr(rh, rl);
            ull imsw = pkr(ih, il);
            vre[m] = f2fma(ccb, vre[m], f2mul(ssb, imsw));
            vim[m] = f2fma(ccb, vim[m], f2mul(nssb, resw));
        }
    }
}

// expectation values on slot bit K -> feature wire
template<int K>
__device__ __forceinline__ void expv_p(const ull* vre, const ull* vim, int wireW,
                                       int lane, int warp, float* s_red) {
    ull zzp = 0, zzn = 0, xr2 = 0, yip = 0, yin = 0;
    #pragma unroll
    for (int m = 0; m < 8; m++) {
        if (((m >> K) & 1) == 0) {
            int m1 = m | (1 << K);
            ull r0 = vre[m], i0 = vim[m], r1 = vre[m1], i1 = vim[m1];
            zzp = f2fma(r0, r0, zzp);  zzp = f2fma(i0, i0, zzp);
            zzn = f2fma(r1, r1, zzn);  zzn = f2fma(i1, i1, zzn);
            xr2 = f2fma(r0, r1, xr2);  xr2 = f2fma(i0, i1, xr2);
            yip = f2fma(r0, i1, yip);  yin = f2fma(i0, r1, yin);
        }
    }
    float a, b;
    upk(zzp, a, b); float zz = a + b;
    upk(zzn, a, b); zz -= a + b;
    upk(xr2, a, b); float xr = a + b;
    upk(yip, a, b); float yi = a + b;
    upk(yin, a, b); yi -= a + b;
    #pragma unroll
    for (int o = 16; o; o >>= 1) {
        xr += __shfl_down_sync(0xffffffffu, xr, o);
        yi += __shfl_down_sync(0xffffffffu, yi, o);
        zz += __shfl_down_sync(0xffffffffu, zz, o);
    }
    if (lane == 0) {
        s_red[wireW * 8 + warp]        = 2.f * xr;
        s_red[(12 + wireW) * 8 + warp] = 2.f * yi;
        s_red[(24 + wireW) * 8 + warp] = zz;
    }
}

// expectation values on pack bit k3 -> feature wire
__device__ __forceinline__ void expv_k3(const ull* vre, const ull* vim, int wireW,
                                        int lane, int warp, float* s_red) {
    float xr = 0.f, yi = 0.f, zz = 0.f;
    #pragma unroll
    for (int m = 0; m < 8; m++) {
        float rl, rh, il, ih;
        upk(vre[m], rl, rh);
        upk(vim[m], il, ih);
        zz += rl * rl + il * il - rh * rh - ih * ih;
        xr += rl * rh + il * ih;
        yi += rl * ih - il * rh;
    }
    #pragma unroll
    for (int o = 16; o; o >>= 1) {
        xr += __shfl_down_sync(0xffffffffu, xr, o);
        yi += __shfl_down_sync(0xffffffffu, yi, o);
        zz += __shfl_down_sync(0xffffffffu, zz, o);
    }
    if (lane == 0) {
        s_red[wireW * 8 + warp]        = 2.f * xr;
        s_red[(12 + wireW) * 8 + warp] = 2.f * yi;
        s_red[(24 + wireW) * 8 + warp] = zz;
    }
}

// ---------------------------------------------------------------------------
__global__ __launch_bounds__(NT, 3)
void sim_kernel(const float* __restrict__ sv,
                const float* __restrict__ W,
                const float* __restrict__ bvec,
                float* __restrict__ out) {
    __shared__ float2 s[4352];           // padded state: 4096 + 256
    __shared__ float  s_red[36 * 8];
    __shared__ float  s_feat[36];
    __shared__ ull    sg1[2][NQ][18];
    __shared__ ull    sgc[2][NQ][6];

    const int tid  = threadIdx.x;
    const int lane = tid & 31;
    const int warp = tid >> 5;
    const int bidx = blockIdx.x;

    {
        ull* dst = &sg1[0][0][0];
        const ull* src = &d_g1[0][0][0];
        for (int i = tid; i < 2 * NQ * 18; i += NT) dst[i] = src[i];
        ull* dst2 = &sgc[0][0][0];
        const ull* src2 = &d_gc[0][0][0];
        for (int i = tid; i < 2 * NQ * 6; i += NT) dst2[i] = src2[i];
    }

    // Load state (real input) straight into packed config-A registers:
    // amp index a = tid | (j<<8); j bit3 (k3/pack) <-> address bit 11 (+2048).
    ull vre[8], vim[8];
    const float* g = sv + (size_t)bidx * DIM;
    #pragma unroll
    for (int m = 0; m < 8; m++) {
        vre[m] = pkr(g[tid + (m << 8)], g[tid + (m << 8) + 2048]);
        vim[m] = 0ull;
    }
    __syncthreads();   // params visible

    // ================= Layer 0 =================
    // config A: k0<->bit8(w3) k1<->bit9(w2) k2<->bit10(w1) k3<->bit11(w0)
    pgate1q_k3(vre, vim, sg1[0][0]);
    pgate1q<2>(vre, vim, sg1[0][1]);
    pgate1q<1>(vre, vim, sg1[0][2]);
    pgate1q<0>(vre, vim, sg1[0][3]);
    pcrx_c3<2>(vre, vim, sgc[0][0]);   // CRX(w0->w1) bits (11,10)
    pcrx<2, 1>(vre, vim, sgc[0][1]);   // (10,9)
    pcrx<1, 0>(vre, vim, sgc[0][2]);   // (9,8)
    remap<0, 1>(vre, vim, s, lane, warp);

    // config B: k0<->bit5(w6) k1<->bit6(w5) k2<->bit7(w4) k3<->bit8(w3)
    pgate1q<2>(vre, vim, sg1[0][4]);
    pgate1q<1>(vre, vim, sg1[0][5]);
    pgate1q<0>(vre, vim, sg1[0][6]);
    pcrx_c3<2>(vre, vim, sgc[0][3]);   // (8,7)
    pcrx<2, 1>(vre, vim, sgc[0][4]);   // (7,6)
    pcrx<1, 0>(vre, vim, sgc[0][5]);   // (6,5)
    remap<1, 2>(vre, vim, s, lane, warp);

    // config C: k0<->bit2(w9) k1<->bit3(w8) k2<->bit4(w7) k3<->bit5(w6)
    pgate1q<2>(vre, vim, sg1[0][7]);
    pgate1q<1>(vre, vim, sg1[0][8]);
    pgate1q<0>(vre, vim, sg1[0][9]);
    pcrx_c3<2>(vre, vim, sgc[0][6]);   // (5,4)
    pcrx<2, 1>(vre, vim, sgc[0][7]);   // (4,3)
    pcrx<1, 0>(vre, vim, sgc[0][8]);   // (3,2)
    remap<2, 3>(vre, vim, s, lane, warp);

    // config D: k0<->bit0(w11) k1<->bit1(w10) k2<->bit2(w9) k3<->bit11(w0)
    pgate1q<1>(vre, vim, sg1[0][10]);
    pgate1q<0>(vre, vim, sg1[0][11]);
    pcrx<2, 1>(vre, vim, sgc[0][9]);   // (2,1)
    pcrx<1, 0>(vre, vim, sgc[0][10]);  // (1,0)
    pcrx_t3<0>(vre, vim, sgc[0][11]);  // (0,11): target = pack bit

    // ================= Layer 1 (starts in config D) =================
    pgate1q_k3(vre, vim, sg1[1][0]);
    pgate1q<2>(vre, vim, sg1[1][9]);
    pgate1q<1>(vre, vim, sg1[1][10]);
    pgate1q<0>(vre, vim, sg1[1][11]);
    pcrx_t3<0>(vre, vim, sgc[1][11]);  // (0,11)
    pcrx<1, 0>(vre, vim, sgc[1][10]);  // (1,0)
    pcrx<2, 1>(vre, vim, sgc[1][9]);   // (2,1)
    remap<3, 2>(vre, vim, s, lane, warp);

    // config C
    pgate1q_k3(vre, vim, sg1[1][6]);
    pgate1q<2>(vre, vim, sg1[1][7]);
    pgate1q<1>(vre, vim, sg1[1][8]);
    pcrx<1, 0>(vre, vim, sgc[1][8]);   // (3,2)
    pcrx<2, 1>(vre, vim, sgc[1][7]);   // (4,3)
    pcrx_c3<2>(vre, vim, sgc[1][6]);   // (5,4): control = pack bit
    remap<2, 1>(vre, vim, s, lane, warp);

    // config B
    pgate1q_k3(vre, vim, sg1[1][3]);
    pgate1q<2>(vre, vim, sg1[1][4]);
    pgate1q<1>(vre, vim, sg1[1][5]);
    pcrx<1, 0>(vre, vim, sgc[1][5]);   // (6,5)
    pcrx<2, 1>(vre, vim, sgc[1][4]);   // (7,6)
    pcrx_c3<2>(vre, vim, sgc[1][3]);   // (8,7)
    remap<1, 0>(vre, vim, s, lane, warp);

    // config A
    pgate1q<2>(vre, vim, sg1[1][1]);
    pgate1q<1>(vre, vim, sg1[1][2]);
    pcrx<1, 0>(vre, vim, sgc[1][2]);   // (9,8)
    pcrx<2, 1>(vre, vim, sgc[1][1]);   // (10,9)
    pcrx_c3<2>(vre, vim, sgc[1][0]);   // (11,10)

    // ================= Expectation values =================
    // config A: local bits 8..11 -> wires 3,2,1,0
    expv_p<0>(vre, vim, 3, lane, warp, s_red);
    expv_p<1>(vre, vim, 2, lane, warp, s_red);
    expv_p<2>(vre, vim, 1, lane, warp, s_red);
    expv_k3 (vre, vim, 0, lane, warp, s_red);
    remap<0, 4>(vre, vim, s, lane, warp);
    // config E: local bits 4..7 -> wires 7,6,5,4
    expv_p<0>(vre, vim, 7, lane, warp, s_red);
    expv_p<1>(vre, vim, 6, lane, warp, s_red);
    expv_p<2>(vre, vim, 5, lane, warp, s_red);
    expv_k3 (vre, vim, 4, lane, warp, s_red);
    remap<4, 5>(vre, vim, s, lane, warp);
    // config F: local bits 0..3 -> wires 11,10,9,8
    expv_p<0>(vre, vim, 11, lane, warp, s_red);
    expv_p<1>(vre, vim, 10, lane, warp, s_red);
    expv_p<2>(vre, vim, 9,  lane, warp, s_red);
    expv_k3 (vre, vim, 8,  lane, warp, s_red);
    __syncthreads();

    if (tid < 36) {
        float f = 0.f;
        #pragma unroll
        for (int r = 0; r < 8; r++) f += s_red[tid * 8 + r];
        s_feat[tid] = f;
    }
    __syncthreads();

    if (tid < 10) {
        float acc = bvec[tid];
        #pragma unroll
        for (int j = 0; j < 36; j++) acc += W[tid * 36 + j] * s_feat[j];
        out[(size_t)bidx * 10 + tid] = acc;
    }
}

extern "C" void kernel_launch(void* const* d_in, const int* in_sizes, int n_in,
                              void* d_out, int out_size) {
    const float* sv     = (const float*)d_in[0];   // [2048, 4096]
    const float* angles = (const float*)d_in[1];   // [96]
    const float* W      = (const float*)d_in[2];   // [10, 36]
    const float* b      = (const float*)d_in[3];   // [10]
    float* out = (float*)d_out;                    // [2048, 10]

    prep_gates<<<1, 32>>>(angles);
    sim_kernel<<<2048, NT>>>(sv, W, b, out);
}

// round 15
// speedup vs baseline: 1.1336x; 1.1336x over previous
#include <cuda_runtime.h>
#include <cstdint>

#define NQ   12
#define DIM  4096
#define NT   256

typedef unsigned long long ull;

// Packed broadcast gate constants (written by prep kernel each launch).
// d_g1[l][w][0..11]: 1q gate coeff packs (same value both lanes);
// d_gc[l][w][0..2]: CRX cc, ss, -ss packs.
__device__ ull d_g1[2][NQ][12];
__device__ ull d_gc[2][NQ][3];

__device__ __forceinline__ float2 cmulf(float2 a, float2 b) {
    return make_float2(a.x * b.x - a.y * b.y, a.x * b.y + a.y * b.x);
}
__device__ __forceinline__ ull pk2(float lo, float hi) {
    return (ull)__float_as_uint(lo) | ((ull)__float_as_uint(hi) << 32);
}

// ---- packed f32x2 ops (Blackwell FFMA2 path, PTX-only) ----
__device__ __forceinline__ ull f2fma(ull a, ull b, ull c) {
    ull d; asm("fma.rn.f32x2 %0, %1, %2, %3;" : "=l"(d) : "l"(a), "l"(b), "l"(c));
    return d;
}
__device__ __forceinline__ ull f2mul(ull a, ull b) {
    ull d; asm("mul.rn.f32x2 %0, %1, %2;" : "=l"(d) : "l"(a), "l"(b));
    return d;
}
__device__ __forceinline__ ull f2add(ull a, ull b) {
    ull d; asm("add.rn.f32x2 %0, %1, %2;" : "=l"(d) : "l"(a), "l"(b));
    return d;
}
__device__ __forceinline__ ull pkr(float lo, float hi) {
    ull r; asm("mov.b64 %0, {%1, %2};" : "=l"(r) : "f"(lo), "f"(hi));
    return r;
}
__device__ __forceinline__ void upk(ull v, float& lo, float& hi) {
    asm("mov.b64 {%0, %1}, %2;" : "=f"(lo), "=f"(hi) : "l"(v));
}

// ---------------------------------------------------------------------------
__global__ void prep_gates(const float* __restrict__ angles) {
    int t = threadIdx.x;
    if (t >= 24) return;
    int l = t / NQ;
    int i = t % NQ;
    int base = l * 48;
    float ax = angles[base + i];
    float ay = angles[base + NQ + i];
    float az = angles[base + 2 * NQ + i];

    float cx = cosf(0.5f * ax), sx = sinf(0.5f * ax);
    float cy = cosf(0.5f * ay), sy = sinf(0.5f * ay);
    float cz = cosf(0.5f * az), sz = sinf(0.5f * az);

    float2 m00 = make_float2(cy * cx,  sy * sx);
    float2 m01 = make_float2(-sy * cx, -cy * sx);
    float2 m10 = make_float2(sy * cx,  -cy * sx);
    float2 m11 = make_float2(cy * cx,  -sy * sx);
    float2 em = make_float2(cz, -sz);
    float2 ep = make_float2(cz,  sz);
    float2 u00 = cmulf(em, m00);
    float2 u01 = cmulf(em, m01);
    float2 u10 = cmulf(ep, m10);
    float2 u11 = cmulf(ep, m11);

    ull* g1 = d_g1[l][i];
    g1[0]  = pk2(u00.x, u00.x);  g1[1]  = pk2(u00.y, u00.y);  g1[2]  = pk2(-u00.y, -u00.y);
    g1[3]  = pk2(u01.x, u01.x);  g1[4]  = pk2(u01.y, u01.y);  g1[5]  = pk2(-u01.y, -u01.y);
    g1[6]  = pk2(u10.x, u10.x);  g1[7]  = pk2(u10.y, u10.y);  g1[8]  = pk2(-u10.y, -u10.y);
    g1[9]  = pk2(u11.x, u11.x);  g1[10] = pk2(u11.y, u11.y);  g1[11] = pk2(-u11.y, -u11.y);

    int g = (l == 0) ? (36 + i) : (84 + (NQ - 1 - i));
    float th = angles[g];
    float cc = cosf(0.5f * th), ss = sinf(0.5f * th);
    ull* gc = d_gc[l][i];
    gc[0] = pk2(cc, cc);   gc[1] = pk2(ss, ss);   gc[2] = pk2(-ss, -ss);
}

// ---------------------------------------------------------------------------
// Layout configs (identical to verified R3 kernel). Address bit b <-> wire (11-b).
//  cfg 0 (A): local bits {8,9,10,11}   cfg 1 (B): {5,6,7,8}   cfg 2 (C): {2,3,4,5}
//  cfg 3 (D): {0,1,2,11}               cfg 4 (E): {4,5,6,7}   cfg 5 (F): {0,1,2,3}
// p = a + (a>>4) padding keeps every config's pattern bank-conflict-free
// (8-byte elements, same pattern as the proven float2 version).
__device__ __forceinline__ int padidx(int a) { return a + (a >> 4); }

template<int CFG>
__device__ __forceinline__ int baseof(int lane, int warp) {
    if (CFG == 0) return lane | (warp << 5);
    if (CFG == 1) return lane | (warp << 9);
    if (CFG == 2) return (lane & 3) | ((lane >> 2) << 6) | (warp << 9);
    if (CFG == 3) return (lane << 3) | (warp << 8);
    if (CFG == 4) return (lane & 15) | ((lane >> 4) << 8) | (warp << 9);
    return (lane << 4) | (warp << 9);
}
template<int CFG>
__device__ __forceinline__ int placeof(int j) {
    if (CFG == 0) return j << 8;
    if (CFG == 1) return j << 5;
    if (CFG == 2) return j << 2;
    if (CFG == 3) return (j & 7) | ((j >> 3) << 11);
    if (CFG == 4) return j << 4;
    return j;
}

// State: vre[m], vim[m] for m = local bits k3k2k1k0 (16 slots per thread).
// Each u64 packs (state0, state1). Remap in two planes through ONE smem array.
template<int CX, int CY>
__device__ __forceinline__ void remap(ull* vre, ull* vim, ull* s, int lane, int warp) {
    const int bx = baseof<CX>(lane, warp);
    const int by = baseof<CY>(lane, warp);
    #pragma unroll
    for (int m = 0; m < 16; m++) s[padidx(bx | placeof<CX>(m))] = vre[m];
    __syncthreads();
    #pragma unroll
    for (int m = 0; m < 16; m++) vre[m] = s[padidx(by | placeof<CY>(m))];
    __syncthreads();
    #pragma unroll
    for (int m = 0; m < 16; m++) s[padidx(bx | placeof<CX>(m))] = vim[m];
    __syncthreads();
    #pragma unroll
    for (int m = 0; m < 16; m++) vim[m] = s[padidx(by | placeof<CY>(m))];
    __syncthreads();
}

// fused 1q gate on local bit K (0..3) — fully packed, no special cases
template<int K>
__device__ __forceinline__ void pgate1q(ull* vre, ull* vim, const ull* c) {
    const ull c0 = c[0], c1 = c[1], c2 = c[2], c3 = c[3], c4 = c[4], c5 = c[5];
    const ull c6 = c[6], c7 = c[7], c8 = c[8], c9 = c[9], c10 = c[10], c11 = c[11];
    #pragma unroll
    for (int m = 0; m < 16; m++) {
        if (((m >> K) & 1) == 0) {
            int m1 = m | (1 << K);
            ull r0 = vre[m], i0 = vim[m], r1 = vre[m1], i1 = vim[m1];
            vre[m]  = f2fma(c0, r0, f2fma(c2, i0, f2fma(c3, r1, f2mul(c5, i1))));
            vim[m]  = f2fma(c0, i0, f2fma(c1, r0, f2fma(c3, i1, f2mul(c4, r1))));
            vre[m1] = f2fma(c6, r0, f2fma(c8, i0, f2fma(c9, r1, f2mul(c11, i1))));
            vim[m1] = f2fma(c6, i0, f2fma(c7, r0, f2fma(c9, i1, f2mul(c10, r1))));
        }
    }
}

// CRX: control bit CK, target bit TK — fully packed
template<int CK, int TK>
__device__ __forceinline__ void pcrx(ull* vre, ull* vim, const ull* gc) {
    const ull ccb = gc[0], ssb = gc[1], nssb = gc[2];
    #pragma unroll
    for (int m = 0; m < 16; m++) {
        if (((m >> CK) & 1) == 1 && ((m >> TK) & 1) == 0) {
            int m1 = m | (1 << TK);
            ull r0 = vre[m], i0 = vim[m], r1 = vre[m1], i1 = vim[m1];
            vre[m]  = f2fma(ccb, r0, f2mul(ssb, i1));
            vim[m]  = f2fma(ccb, i0, f2mul(nssb, r1));
            vre[m1] = f2fma(ccb, r1, f2mul(ssb, i0));
            vim[m1] = f2fma(ccb, i1, f2mul(nssb, r0));
        }
    }
}

// expectation values on local bit K -> feature wire (packed through the reduction)
template<int K>
__device__ __forceinline__ void expv(const ull* vre, const ull* vim, int wireW,
                                     int lane, int warp, ull* s_red) {
    ull zzp = 0, zzn = 0, xr = 0, yip = 0, yin = 0;
    #pragma unroll
    for (int m = 0; m < 16; m++) {
        if (((m >> K) & 1) == 0) {
            int m1 = m | (1 << K);
            ull r0 = vre[m], i0 = vim[m], r1 = vre[m1], i1 = vim[m1];
            zzp = f2fma(r0, r0, zzp);  zzp = f2fma(i0, i0, zzp);
            zzn = f2fma(r1, r1, zzn);  zzn = f2fma(i1, i1, zzn);
            xr  = f2fma(r0, r1, xr);   xr  = f2fma(i0, i1, xr);
            yip = f2fma(r0, i1, yip);  yin = f2fma(i0, r1, yin);
        }
    }
    const ull n1 = pk2(-1.f, -1.f);
    ull zz = f2fma(n1, zzn, zzp);
    ull yi = f2fma(n1, yin, yip);
    #pragma unroll
    for (int o = 16; o; o >>= 1) {
        xr = f2add(xr, __shfl_down_sync(0xffffffffu, xr, o));
        yi = f2add(yi, __shfl_down_sync(0xffffffffu, yi, o));
        zz = f2add(zz, __shfl_down_sync(0xffffffffu, zz, o));
    }
    if (lane == 0) {
        s_red[wireW * 8 + warp]        = xr;   // X (x2 applied later)
        s_red[(12 + wireW) * 8 + warp] = yi;   // Y (x2 applied later)
        s_red[(24 + wireW) * 8 + warp] = zz;   // Z
    }
}

// ---------------------------------------------------------------------------
__global__ __launch_bounds__(NT, 2)
void sim_kernel(const float* __restrict__ sv,
                const float* __restrict__ W,
                const float* __restrict__ bvec,
                float* __restrict__ out) {
    __shared__ ull s[4352];              // padded packed state plane: 34.8 KB
    __shared__ ull s_red[36 * 8];
    __shared__ ull s_feat[36];
    __shared__ ull sg1[2][NQ][12];
    __shared__ ull sgc[2][NQ][3];

    const int tid  = threadIdx.x;
    const int lane = tid & 31;
    const int warp = tid >> 5;
    const int bidx = blockIdx.x;

    {
        ull* dst = &sg1[0][0][0];
        const ull* src = &d_g1[0][0][0];
        for (int i = tid; i < 2 * NQ * 12; i += NT) dst[i] = src[i];
        ull* dst2 = &sgc[0][0][0];
        const ull* src2 = &d_gc[0][0][0];
        for (int i = tid; i < 2 * NQ * 3; i += NT) dst2[i] = src2[i];
    }

    // Two states per CTA, packed (state0, state1) in each u64.
    // Config A layout: amp index a = tid | (m<<8) -> coalesced per m per state.
    ull vre[16], vim[16];
    const float* g0 = sv + (size_t)(2 * bidx) * DIM;
    const float* g1 = g0 + DIM;
    #pragma unroll
    for (int m = 0; m < 16; m++) {
        int a = tid | (m << 8);
        vre[m] = pkr(g0[a], g1[a]);
        vim[m] = 0ull;
    }
    __syncthreads();   // params visible

    // ================= Layer 0 =================
    // config A: k0<->bit8(w3) k1<->bit9(w2) k2<->bit10(w1) k3<->bit11(w0)
    pgate1q<3>(vre, vim, sg1[0][0]);
    pgate1q<2>(vre, vim, sg1[0][1]);
    pgate1q<1>(vre, vim, sg1[0][2]);
    pgate1q<0>(vre, vim, sg1[0][3]);
    pcrx<3, 2>(vre, vim, sgc[0][0]);   // CRX(w0->w1) bits (11,10)
    pcrx<2, 1>(vre, vim, sgc[0][1]);   // (10,9)
    pcrx<1, 0>(vre, vim, sgc[0][2]);   // (9,8)
    remap<0, 1>(vre, vim, s, lane, warp);

    // config B: k0<->bit5(w6) k1<->bit6(w5) k2<->bit7(w4) k3<->bit8(w3)
    pgate1q<2>(vre, vim, sg1[0][4]);
    pgate1q<1>(vre, vim, sg1[0][5]);
    pgate1q<0>(vre, vim, sg1[0][6]);
    pcrx<3, 2>(vre, vim, sgc[0][3]);   // (8,7)
    pcrx<2, 1>(vre, vim, sgc[0][4]);   // (7,6)
    pcrx<1, 0>(vre, vim, sgc[0][5]);   // (6,5)
    remap<1, 2>(vre, vim, s, lane, warp);

    // config C: k0<->bit2(w9) k1<->bit3(w8) k2<->bit4(w7) k3<->bit5(w6)
    pgate1q<2>(vre, vim, sg1[0][7]);
    pgate1q<1>(vre, vim, sg1[0][8]);
    pgate1q<0>(vre, vim, sg1[0][9]);
    pcrx<3, 2>(vre, vim, sgc[0][6]);   // (5,4)
    pcrx<2, 1>(vre, vim, sgc[0][7]);   // (4,3)
    pcrx<1, 0>(vre, vim, sgc[0][8]);   // (3,2)
    remap<2, 3>(vre, vim, s, lane, warp);

    // config D: k0<->bit0(w11) k1<->bit1(w10) k2<->bit2(w9) k3<->bit11(w0)
    pgate1q<1>(vre, vim, sg1[0][10]);
    pgate1q<0>(vre, vim, sg1[0][11]);
    pcrx<2, 1>(vre, vim, sgc[0][9]);   // (2,1)
    pcrx<1, 0>(vre, vim, sgc[0][10]);  // (1,0)
    pcrx<0, 3>(vre, vim, sgc[0][11]);  // (0,11)

    // ================= Layer 1 (starts in config D) =================
    pgate1q<3>(vre, vim, sg1[1][0]);
    pgate1q<2>(vre, vim, sg1[1][9]);
    pgate1q<1>(vre, vim, sg1[1][10]);
    pgate1q<0>(vre, vim, sg1[1][11]);
    pcrx<0, 3>(vre, vim, sgc[1][11]);  // (0,11)
    pcrx<1, 0>(vre, vim, sgc[1][10]);  // (1,0)
    pcrx<2, 1>(vre, vim, sgc[1][9]);   // (2,1)
    remap<3, 2>(vre, vim, s, lane, warp);

    // config C
    pgate1q<3>(vre, vim, sg1[1][6]);
    pgate1q<2>(vre, vim, sg1[1][7]);
    pgate1q<1>(vre, vim, sg1[1][8]);
    pcrx<1, 0>(vre, vim, sgc[1][8]);   // (3,2)
    pcrx<2, 1>(vre, vim, sgc[1][7]);   // (4,3)
    pcrx<3, 2>(vre, vim, sgc[1][6]);   // (5,4)
    remap<2, 1>(vre, vim, s, lane, warp);

    // config B
    pgate1q<3>(vre, vim, sg1[1][3]);
    pgate1q<2>(vre, vim, sg1[1][4]);
    pgate1q<1>(vre, vim, sg1[1][5]);
    pcrx<1, 0>(vre, vim, sgc[1][5]);   // (6,5)
    pcrx<2, 1>(vre, vim, sgc[1][4]);   // (7,6)
    pcrx<3, 2>(vre, vim, sgc[1][3]);   // (8,7)
    remap<1, 0>(vre, vim, s, lane, warp);

    // config A
    pgate1q<2>(vre, vim, sg1[1][1]);
    pgate1q<1>(vre, vim, sg1[1][2]);
    pcrx<1, 0>(vre, vim, sgc[1][2]);   // (9,8)
    pcrx<2, 1>(vre, vim, sgc[1][1]);   // (10,9)
    pcrx<3, 2>(vre, vim, sgc[1][0]);   // (11,10)

    // ================= Expectation values =================
    // config A: local bits 8..11 -> wires 3,2,1,0
    expv<0>(vre, vim, 3, lane, warp, s_red);
    expv<1>(vre, vim, 2, lane, warp, s_red);
    expv<2>(vre, vim, 1, lane, warp, s_red);
    expv<3>(vre, vim, 0, lane, warp, s_red);
    remap<0, 4>(vre, vim, s, lane, warp);
    // config E: local bits 4..7 -> wires 7,6,5,4
    expv<0>(vre, vim, 7, lane, warp, s_red);
    expv<1>(vre, vim, 6, lane, warp, s_red);
    expv<2>(vre, vim, 5, lane, warp, s_red);
    expv<3>(vre, vim, 4, lane, warp, s_red);
    remap<4, 5>(vre, vim, s, lane, warp);
    // config F: local bits 0..3 -> wires 11,10,9,8
    expv<0>(vre, vim, 11, lane, warp, s_red);
    expv<1>(vre, vim, 10, lane, warp, s_red);
    expv<2>(vre, vim, 9,  lane, warp, s_red);
    expv<3>(vre, vim, 8,  lane, warp, s_red);
    __syncthreads();

    if (tid < 36) {
        ull f = s_red[tid * 8];
        #pragma unroll
        for (int r = 1; r < 8; r++) f = f2add(f, s_red[tid * 8 + r]);
        if (tid < 24) f = f2add(f, f);   // the 2x factor for X and Y features
        s_feat[tid] = f;
    }
    __syncthreads();

    if (tid < 10) {
        float bb = bvec[tid];
        ull acc = pkr(bb, bb);
        #pragma unroll
        for (int j = 0; j < 36; j++) {
            float wj = W[tid * 36 + j];
            acc = f2fma(pkr(wj, wj), s_feat[j], acc);
        }
        float o0, o1;
        upk(acc, o0, o1);
        out[(size_t)(2 * bidx) * 10 + tid]     = o0;
        out[(size_t)(2 * bidx + 1) * 10 + tid] = o1;
    }
}

extern "C" void kernel_launch(void* const* d_in, const int* in_sizes, int n_in,
                              void* d_out, int out_size) {
    const float* sv     = (const float*)d_in[0];   // [2048, 4096]
    const float* angles = (const float*)d_in[1];   // [96]
    const float* W      = (const float*)d_in[2];   // [10, 36]
    const float* b      = (const float*)d_in[3];   // [10]
    float* out = (float*)d_out;                    // [2048, 10]

    prep_gates<<<1, 32>>>(angles);
    sim_kernel<<<1024, NT>>>(sv, W, b, out);
}